// round 3
// baseline (speedup 1.0000x reference)
#include <cuda_runtime.h>
#include <cuda_bf16.h>

// DenseIouPred: 72x72 IoU map around ind[0], window radius r.
// Scatter inverts to per-pixel gather (valid offsets <-> in-range pixels 1:1,
// gather index == own flat index).
// R3: revert to best-measured config (21x256, scalar, low regs) + branchless
// predication + unconditional hoisted loads. Kernel is launch-overhead-bound
// (all pipes <0.5% in ncu), so keep the structure that measured fastest.

#define W 72
#define H 72
#define NPIX (W * H)   // 5184

__device__ int g_default_radius = 10;

__global__ void __launch_bounds__(256, 8)
dense_iou_kernel(const float* __restrict__ out0,   // (4, W, H)
                 const int*   __restrict__ ind,
                 const float* __restrict__ tgt,    // 4 floats
                 const int*   __restrict__ radius_p,
                 float*       __restrict__ dst)    // (W, H)
{
    const int i = blockIdx.x * blockDim.x + threadIdx.x;
    if (i >= NPIX) return;

    // All loads issued unconditionally, mutually independent (MLP ~ 7).
    const int   ind0 = __ldg(ind);
    const int   r    = __ldg(radius_p);
    const float tl   = __ldg(tgt + 0);
    const float tr   = __ldg(tgt + 1);
    const float tt   = __ldg(tgt + 2);
    const float tb   = __ldg(tgt + 3);
    const float pl   = __ldg(out0 + 0 * NPIX + i);
    const float pr   = __ldg(out0 + 1 * NPIX + i);
    const float pt   = __ldg(out0 + 2 * NPIX + i);
    const float pb   = __ldg(out0 + 3 * NPIX + i);

    const int row = i / W;
    const int col = i - row * W;
    const int cw  = ind0 % W;
    const int ch  = ind0 / W;

    const int rw = col - cw;
    const int rh = row - ch;

    const float frw = (float)rw;
    const float frh = (float)rh;
    const float twl = tl + frw;
    const float twr = tr - frw;
    const float tht = tt + frh;
    const float thb = tb - frh;

    // Branchless validity
    const bool valid =
        (rw >= -r) & (rw <= r) & (rh >= -r) & (rh <= r) &
        (twl >= 0.0f) & (twr >= 0.0f) & (tht >= 0.0f) & (thb >= 0.0f);

    const float target_area = (twl + twr) * (tht + thb);
    const float pred_area   = (pl + pr) * (pt + pb);
    const float w_int = fminf(pl, twl) + fminf(pr, twr);
    const float h_int = fminf(pb, thb) + fminf(pt, tht);
    const float area_int   = w_int * h_int;
    const float area_union = target_area + pred_area - area_int;
    const float iou = __fdividef(area_int + 1.0f, area_union + 1.0f);

    dst[i] = valid ? iou : 0.0f;
}

extern "C" void kernel_launch(void* const* d_in, const int* in_sizes, int n_in,
                              void* d_out, int out_size)
{
    const float* output = (const float*)d_in[0];   // (128, 8, 4, 72, 72)
    const int*   ind    = (const int*)  d_in[1];   // (128, 8, 1)
    const float* target = (const float*)d_in[2];   // (128, 8, 4)
    float*       dst    = (float*)d_out;           // (72, 72)

    const int* radius = nullptr;
    if (n_in >= 4) {
        radius = (const int*)d_in[3];
    } else {
        void* p = nullptr;
        cudaGetSymbolAddress(&p, g_default_radius);  // capture-safe, no alloc
        radius = (const int*)p;
    }

    const int threads = 256;
    const int blocks  = (NPIX + threads - 1) / threads;  // 21
    dense_iou_kernel<<<blocks, threads>>>(output, ind, target, radius, dst);
}

// round 4
// speedup vs baseline: 1.2000x; 1.2000x over previous
#include <cuda_runtime.h>
#include <cuda_bf16.h>

// DenseIouPred: 72x72 IoU map around ind[0], window radius r.
// Scatter inverts to per-pixel gather (valid offsets <-> in-range pixels 1:1,
// gather index == own flat index).
// R4: keep R3's branchless hoisted-load body (best ncu kernel time, 4.51us);
// reshape launch to 41 CTAs x 128 threads (one wave, 4 warps/CTA -> 1 warp
// per SMSP, faster CTA drain). Kernel is launch-overhead bound; this targets
// the T_CTA + tail component.

#define W 72
#define H 72
#define NPIX (W * H)   // 5184

__device__ int g_default_radius = 10;

__global__ void dense_iou_kernel(const float* __restrict__ out0,   // (4, W, H)
                                 const int*   __restrict__ ind,
                                 const float* __restrict__ tgt,    // 4 floats
                                 const int*   __restrict__ radius_p,
                                 float*       __restrict__ dst)    // (W, H)
{
    const int i = blockIdx.x * blockDim.x + threadIdx.x;
    if (i >= NPIX) return;

    // All loads issued unconditionally, mutually independent (MLP ~ 7).
    const int   ind0 = __ldg(ind);
    const int   r    = __ldg(radius_p);
    const float tl   = __ldg(tgt + 0);
    const float tr   = __ldg(tgt + 1);
    const float tt   = __ldg(tgt + 2);
    const float tb   = __ldg(tgt + 3);
    const float pl   = __ldg(out0 + 0 * NPIX + i);
    const float pr   = __ldg(out0 + 1 * NPIX + i);
    const float pt   = __ldg(out0 + 2 * NPIX + i);
    const float pb   = __ldg(out0 + 3 * NPIX + i);

    const int row = i / W;
    const int col = i - row * W;
    const int cw  = ind0 % W;
    const int ch  = ind0 / W;

    const int rw = col - cw;
    const int rh = row - ch;

    const float frw = (float)rw;
    const float frh = (float)rh;
    const float twl = tl + frw;
    const float twr = tr - frw;
    const float tht = tt + frh;
    const float thb = tb - frh;

    // Branchless validity
    const bool valid =
        (rw >= -r) & (rw <= r) & (rh >= -r) & (rh <= r) &
        (twl >= 0.0f) & (twr >= 0.0f) & (tht >= 0.0f) & (thb >= 0.0f);

    const float target_area = (twl + twr) * (tht + thb);
    const float pred_area   = (pl + pr) * (pt + pb);
    const float w_int = fminf(pl, twl) + fminf(pr, twr);
    const float h_int = fminf(pb, thb) + fminf(pt, tht);
    const float area_int   = w_int * h_int;
    const float area_union = target_area + pred_area - area_int;
    const float iou = __fdividef(area_int + 1.0f, area_union + 1.0f);

    dst[i] = valid ? iou : 0.0f;
}

extern "C" void kernel_launch(void* const* d_in, const int* in_sizes, int n_in,
                              void* d_out, int out_size)
{
    const float* output = (const float*)d_in[0];   // (128, 8, 4, 72, 72)
    const int*   ind    = (const int*)  d_in[1];   // (128, 8, 1)
    const float* target = (const float*)d_in[2];   // (128, 8, 4)
    float*       dst    = (float*)d_out;           // (72, 72)

    const int* radius = nullptr;
    if (n_in >= 4) {
        radius = (const int*)d_in[3];
    } else {
        void* p = nullptr;
        cudaGetSymbolAddress(&p, g_default_radius);  // capture-safe, no alloc
        radius = (const int*)p;
    }

    const int threads = 128;
    const int blocks  = (NPIX + threads - 1) / threads;  // 41 CTAs, one wave
    dense_iou_kernel<<<blocks, threads>>>(output, ind, target, radius, dst);
}